// round 1
// baseline (speedup 1.0000x reference)
#include <cuda_runtime.h>

// ---------------------------------------------------------------------------
// GCN layer:
//   s1[d]  += feature[s]  for each edge (s,d);  deg[d] += 1
//   h_agg   = s1 / max(deg,1)
//   accum   = relu(label@W0 + h_agg@W1 + x@W2 + (b0+b1+b2))
//   out     = relu([accum, h_agg, feature] @ Wa + ba)
//
// Inputs (metadata order):
//  0 feature [N,3] f32   1 x_attr [N,2] f32   2 label [N,1] f32
//  3 W0 [1,3]  4 b0 [3]  5 W1 [3,3]  6 b1 [3] 7 W2 [2,3]  8 b2 [3]
//  9 Wa [9,3] 10 ba [3] 11 src [E] i32       12 dst [E] i32
// Output: [N,3] f32
// ---------------------------------------------------------------------------

#define NODE_CAP 1048576  // N = 1e6 in this problem; cap with headroom

// Scratch accumulator: xyz = sum of neighbor features, w = degree
__device__ float4 g_accum[NODE_CAP];

__global__ void zero_kernel(int n) {
    int i = blockIdx.x * blockDim.x + threadIdx.x;
    if (i < n) g_accum[i] = make_float4(0.f, 0.f, 0.f, 0.f);
}

__device__ __forceinline__ void edge_op(const float* __restrict__ feat, int s, int d) {
    float a = __ldg(feat + 3 * s);
    float b = __ldg(feat + 3 * s + 1);
    float c = __ldg(feat + 3 * s + 2);
    float4* p = g_accum + d;
    asm volatile("red.global.add.v4.f32 [%0], {%1, %2, %3, %4};"
                 :: "l"(p), "f"(a), "f"(b), "f"(c), "f"(1.0f) : "memory");
}

__global__ void edge_kernel(const int* __restrict__ src,
                            const int* __restrict__ dst,
                            const float* __restrict__ feat,
                            int e4, int rem) {
    int i = blockIdx.x * blockDim.x + threadIdx.x;
    if (i < e4) {
        int4 s = reinterpret_cast<const int4*>(src)[i];
        int4 d = reinterpret_cast<const int4*>(dst)[i];
        edge_op(feat, s.x, d.x);
        edge_op(feat, s.y, d.y);
        edge_op(feat, s.z, d.z);
        edge_op(feat, s.w, d.w);
    } else if (i == e4 && rem) {
        int base = e4 * 4;
        for (int k = 0; k < rem; k++)
            edge_op(feat, src[base + k], dst[base + k]);
    }
}

__global__ void node_kernel(const float* __restrict__ feat,
                            const float* __restrict__ x_attr,
                            const float* __restrict__ label,
                            const float* __restrict__ W0, const float* __restrict__ b0,
                            const float* __restrict__ W1, const float* __restrict__ b1,
                            const float* __restrict__ W2, const float* __restrict__ b2,
                            const float* __restrict__ Wa, const float* __restrict__ ba,
                            float* __restrict__ out, int n) {
    __shared__ float sW0[3], sW1[9], sW2[6], sWa[27], sB[3], sBa[3];
    int t = threadIdx.x;
    if (t < 3)  { sW0[t] = W0[t]; sB[t] = b0[t] + b1[t] + b2[t]; sBa[t] = ba[t]; }
    if (t < 9)  sW1[t] = W1[t];
    if (t < 6)  sW2[t] = W2[t];
    if (t < 27) sWa[t] = Wa[t];
    __syncthreads();

    int i = blockIdx.x * blockDim.x + threadIdx.x;
    if (i >= n) return;

    float4 acc = g_accum[i];
    float inv = 1.0f / fmaxf(acc.w, 1.0f);
    float hg0 = acc.x * inv, hg1 = acc.y * inv, hg2 = acc.z * inv;

    float f0 = feat[3 * i], f1 = feat[3 * i + 1], f2 = feat[3 * i + 2];
    float x0 = x_attr[2 * i], x1 = x_attr[2 * i + 1];
    float lb = label[i];

    // accum_j = relu(lb*W0[j] + hg@W1[:,j] + x@W2[:,j] + B[j])
    float a[3];
#pragma unroll
    for (int j = 0; j < 3; j++) {
        float v = lb * sW0[j]
                + hg0 * sW1[0 * 3 + j] + hg1 * sW1[1 * 3 + j] + hg2 * sW1[2 * 3 + j]
                + x0 * sW2[0 * 3 + j] + x1 * sW2[1 * 3 + j]
                + sB[j];
        a[j] = fmaxf(v, 0.f);
    }

    // z = [a0..2, hg0..2, f0..2];  out_j = relu(z @ Wa[:,j] + ba[j])
#pragma unroll
    for (int j = 0; j < 3; j++) {
        float v = a[0] * sWa[0 * 3 + j] + a[1] * sWa[1 * 3 + j] + a[2] * sWa[2 * 3 + j]
                + hg0 * sWa[3 * 3 + j] + hg1 * sWa[4 * 3 + j] + hg2 * sWa[5 * 3 + j]
                + f0 * sWa[6 * 3 + j] + f1 * sWa[7 * 3 + j] + f2 * sWa[8 * 3 + j]
                + sBa[j];
        out[3 * i + j] = fmaxf(v, 0.f);
    }
}

extern "C" void kernel_launch(void* const* d_in, const int* in_sizes, int n_in,
                              void* d_out, int out_size) {
    const float* feature = (const float*)d_in[0];
    const float* x_attr  = (const float*)d_in[1];
    const float* label   = (const float*)d_in[2];
    const float* W0 = (const float*)d_in[3];
    const float* b0 = (const float*)d_in[4];
    const float* W1 = (const float*)d_in[5];
    const float* b1 = (const float*)d_in[6];
    const float* W2 = (const float*)d_in[7];
    const float* b2 = (const float*)d_in[8];
    const float* Wa = (const float*)d_in[9];
    const float* ba = (const float*)d_in[10];
    const int*   src = (const int*)d_in[11];
    const int*   dst = (const int*)d_in[12];
    float* out = (float*)d_out;

    int N = in_sizes[0] / 3;
    int E = in_sizes[11];
    int e4 = E / 4;
    int rem = E % 4;

    const int TB = 256;
    zero_kernel<<<(N + TB - 1) / TB, TB>>>(N);
    int edge_threads = e4 + (rem ? 1 : 0);
    edge_kernel<<<(edge_threads + TB - 1) / TB, TB>>>(src, dst, feature, e4, rem);
    node_kernel<<<(N + TB - 1) / TB, TB>>>(feature, x_attr, label,
                                           W0, b0, W1, b1, W2, b2, Wa, ba,
                                           out, N);
}

// round 2
// speedup vs baseline: 1.1647x; 1.1647x over previous
#include <cuda_runtime.h>

// ---------------------------------------------------------------------------
// GCN layer (push-mode segment mean + tiny per-node MLPs)
//   R2: repack feature -> float4 (f0,f1,f2,1.0) so the edge gather is one
//   LDG.128 and the degree increment rides in .w of a single REDG.v4.
// ---------------------------------------------------------------------------

#define NODE_CAP 1048576  // N = 1e6 in this problem

// Scratch: xyz = neighbor-feature sum, w = degree
__device__ float4 g_accum[NODE_CAP];
// Repacked features: xyz = feature, w = 1.0
__device__ float4 g_feat[NODE_CAP];

__global__ void prep_kernel(const float* __restrict__ feat, int n) {
    int i = blockIdx.x * blockDim.x + threadIdx.x;
    if (i < n) {
        g_accum[i] = make_float4(0.f, 0.f, 0.f, 0.f);
        g_feat[i]  = make_float4(feat[3 * i], feat[3 * i + 1], feat[3 * i + 2], 1.0f);
    }
}

__device__ __forceinline__ void edge_op(int s, int d) {
    float4 f = __ldg(&g_feat[s]);
    float4* p = g_accum + d;
    asm volatile("red.global.add.v4.f32 [%0], {%1, %2, %3, %4};"
                 :: "l"(p), "f"(f.x), "f"(f.y), "f"(f.z), "f"(f.w) : "memory");
}

__global__ void edge_kernel(const int* __restrict__ src,
                            const int* __restrict__ dst,
                            int e4, int rem) {
    int i = blockIdx.x * blockDim.x + threadIdx.x;
    if (i < e4) {
        int4 s = reinterpret_cast<const int4*>(src)[i];
        int4 d = reinterpret_cast<const int4*>(dst)[i];
        edge_op(s.x, d.x);
        edge_op(s.y, d.y);
        edge_op(s.z, d.z);
        edge_op(s.w, d.w);
    } else if (i == e4 && rem) {
        int base = e4 * 4;
        for (int k = 0; k < rem; k++)
            edge_op(src[base + k], dst[base + k]);
    }
}

__global__ void node_kernel(const float* __restrict__ x_attr,
                            const float* __restrict__ label,
                            const float* __restrict__ W0, const float* __restrict__ b0,
                            const float* __restrict__ W1, const float* __restrict__ b1,
                            const float* __restrict__ W2, const float* __restrict__ b2,
                            const float* __restrict__ Wa, const float* __restrict__ ba,
                            float* __restrict__ out, int n) {
    __shared__ float sW0[3], sW1[9], sW2[6], sWa[27], sB[3], sBa[3];
    int t = threadIdx.x;
    if (t < 3)  { sW0[t] = W0[t]; sB[t] = b0[t] + b1[t] + b2[t]; sBa[t] = ba[t]; }
    if (t < 9)  sW1[t] = W1[t];
    if (t < 6)  sW2[t] = W2[t];
    if (t < 27) sWa[t] = Wa[t];
    __syncthreads();

    int i = blockIdx.x * blockDim.x + threadIdx.x;
    if (i >= n) return;

    float4 acc = g_accum[i];
    float inv = 1.0f / fmaxf(acc.w, 1.0f);
    float hg0 = acc.x * inv, hg1 = acc.y * inv, hg2 = acc.z * inv;

    float4 f4 = g_feat[i];
    float f0 = f4.x, f1 = f4.y, f2 = f4.z;
    float x0 = x_attr[2 * i], x1 = x_attr[2 * i + 1];
    float lb = label[i];

    float a[3];
#pragma unroll
    for (int j = 0; j < 3; j++) {
        float v = lb * sW0[j]
                + hg0 * sW1[0 * 3 + j] + hg1 * sW1[1 * 3 + j] + hg2 * sW1[2 * 3 + j]
                + x0 * sW2[0 * 3 + j] + x1 * sW2[1 * 3 + j]
                + sB[j];
        a[j] = fmaxf(v, 0.f);
    }

#pragma unroll
    for (int j = 0; j < 3; j++) {
        float v = a[0] * sWa[0 * 3 + j] + a[1] * sWa[1 * 3 + j] + a[2] * sWa[2 * 3 + j]
                + hg0 * sWa[3 * 3 + j] + hg1 * sWa[4 * 3 + j] + hg2 * sWa[5 * 3 + j]
                + f0 * sWa[6 * 3 + j] + f1 * sWa[7 * 3 + j] + f2 * sWa[8 * 3 + j]
                + sBa[j];
        out[3 * i + j] = fmaxf(v, 0.f);
    }
}

extern "C" void kernel_launch(void* const* d_in, const int* in_sizes, int n_in,
                              void* d_out, int out_size) {
    const float* feature = (const float*)d_in[0];
    const float* x_attr  = (const float*)d_in[1];
    const float* label   = (const float*)d_in[2];
    const float* W0 = (const float*)d_in[3];
    const float* b0 = (const float*)d_in[4];
    const float* W1 = (const float*)d_in[5];
    const float* b1 = (const float*)d_in[6];
    const float* W2 = (const float*)d_in[7];
    const float* b2 = (const float*)d_in[8];
    const float* Wa = (const float*)d_in[9];
    const float* ba = (const float*)d_in[10];
    const int*   src = (const int*)d_in[11];
    const int*   dst = (const int*)d_in[12];
    float* out = (float*)d_out;

    int N = in_sizes[0] / 3;
    int E = in_sizes[11];
    int e4 = E / 4;
    int rem = E % 4;

    const int TB = 256;
    prep_kernel<<<(N + TB - 1) / TB, TB>>>(feature, N);
    int edge_threads = e4 + (rem ? 1 : 0);
    edge_kernel<<<(edge_threads + TB - 1) / TB, TB>>>(src, dst, e4, rem);
    node_kernel<<<(N + TB - 1) / TB, TB>>>(x_attr, label,
                                           W0, b0, W1, b1, W2, b2, Wa, ba,
                                           out, N);
}